// round 11
// baseline (speedup 1.0000x reference)
#include <cuda_runtime.h>
#include <cuda_bf16.h>
#include <cstdint>

#define N_NODES 100000
#define F_DIM   256
#define E_DIM   128
#define B_DIM   8192
#define D_DIM   32
#define K_SEL   16
#define CAT_DIM 640   // F + 3E

// ---------------------------------------------------------------------------
// Scratch (static device globals — no allocations allowed)
// ---------------------------------------------------------------------------
__device__ __align__(16) float          g_scores[N_NODES * 2];
__device__ __align__(16) __nv_bfloat16  g_mean_hi[3ULL * B_DIM * F_DIM];   // [r][m][k]
__device__ __align__(16) __nv_bfloat16  g_mean_lo[3ULL * B_DIM * F_DIM];
__device__ __align__(16) __nv_bfloat16  g_cat_hi[(size_t)B_DIM * CAT_DIM]; // [m][k]
__device__ __align__(16) __nv_bfloat16  g_cat_lo[(size_t)B_DIM * CAT_DIM];
__device__ __align__(16) __nv_bfloat16  g_w_hi[3 * F_DIM * E_DIM];         // [r][k][n]
__device__ __align__(16) __nv_bfloat16  g_w_lo[3 * F_DIM * E_DIM];
__device__ __align__(16) __nv_bfloat16  g_wgt_hi[CAT_DIM * E_DIM];         // [k][n]
__device__ __align__(16) __nv_bfloat16  g_wgt_lo[CAT_DIM * E_DIM];
__device__ unsigned int                 g_cnt[B_DIM / 64];                  // per-m-block

// ---------------------------------------------------------------------------
// helpers
// ---------------------------------------------------------------------------
__device__ __forceinline__ uint32_t smem_u32(const void* p) {
    uint32_t a;
    asm("{ .reg .u64 t; cvta.to.shared.u64 t, %1; cvt.u32.u64 %0, t; }" : "=r"(a) : "l"(p));
    return a;
}
__device__ __forceinline__ void bf16split(float x, __nv_bfloat16& h, __nv_bfloat16& l) {
    h = __float2bfloat16(x);
    l = __float2bfloat16(x - __bfloat162float(h));
}
__device__ __forceinline__ uint32_t pack2(__nv_bfloat16 a, __nv_bfloat16 b) {
    __nv_bfloat162 t = __halves2bfloat162(a, b);
    return *reinterpret_cast<uint32_t*>(&t);
}
__device__ __forceinline__ void ldsm4(uint32_t* r, uint32_t addr) {
    asm volatile("ldmatrix.sync.aligned.m8n8.x4.shared.b16 {%0,%1,%2,%3}, [%4];"
                 : "=r"(r[0]), "=r"(r[1]), "=r"(r[2]), "=r"(r[3]) : "r"(addr));
}
__device__ __forceinline__ void ldsm4t(uint32_t* r, uint32_t addr) {
    asm volatile("ldmatrix.sync.aligned.m8n8.x4.trans.shared.b16 {%0,%1,%2,%3}, [%4];"
                 : "=r"(r[0]), "=r"(r[1]), "=r"(r[2]), "=r"(r[3]) : "r"(addr));
}
__device__ __forceinline__ void mma16816(float* c, const uint32_t* a, const uint32_t* b) {
    asm volatile(
        "mma.sync.aligned.m16n8k16.row.col.f32.bf16.bf16.f32 "
        "{%0,%1,%2,%3}, {%4,%5,%6,%7}, {%8,%9}, {%0,%1,%2,%3};"
        : "+f"(c[0]), "+f"(c[1]), "+f"(c[2]), "+f"(c[3])
        : "r"(a[0]), "r"(a[1]), "r"(a[2]), "r"(a[3]), "r"(b[0]), "r"(b[1]));
}
__device__ __forceinline__ void cp16(uint32_t s, const void* g) {
    asm volatile("cp.async.cg.shared.global [%0], [%1], 16;" :: "r"(s), "l"(g));
}
#define CP_COMMIT() asm volatile("cp.async.commit_group;" ::: "memory")
#define CP_WAIT(n)  asm volatile("cp.async.wait_group %0;" :: "n"(n) : "memory")

__device__ __forceinline__ void red_release(unsigned int* p) {
    asm volatile("red.release.gpu.global.add.u32 [%0], 1;" :: "l"(p) : "memory");
}
__device__ __forceinline__ unsigned int ld_acquire(const unsigned int* p) {
    unsigned int v;
    asm volatile("ld.acquire.gpu.global.u32 %0, [%1];" : "=r"(v) : "l"(p) : "memory");
    return v;
}

// ---------------------------------------------------------------------------
// K1: scores[n] = features[n] @ wc + bc (one warp per node)
// ---------------------------------------------------------------------------
__global__ void k_scores(const float* __restrict__ feat, const float* __restrict__ wc,
                         const float* __restrict__ bc) {
    int gwarp = (blockIdx.x * blockDim.x + threadIdx.x) >> 5;
    int lane  = threadIdx.x & 31;
    if (gwarp >= N_NODES) return;
    const float* row = feat + (size_t)gwarp * F_DIM;
    float s0 = 0.f, s1 = 0.f;
#pragma unroll
    for (int k = 0; k < 8; k++) {
        int f = k * 32 + lane;
        float v = row[f];
        s0 += v * __ldg(&wc[f * 2 + 0]);
        s1 += v * __ldg(&wc[f * 2 + 1]);
    }
#pragma unroll
    for (int o = 16; o; o >>= 1) {
        s0 += __shfl_down_sync(0xFFFFFFFFu, s0, o);
        s1 += __shfl_down_sync(0xFFFFFFFFu, s1, o);
    }
    if (lane == 0) {
        g_scores[gwarp * 2 + 0] = s0 + bc[0];
        g_scores[gwarp * 2 + 1] = s1 + bc[1];
    }
}

// ---------------------------------------------------------------------------
// K2: self features -> g_cat cols [0,256) + center scores (4 rows / block)
// ---------------------------------------------------------------------------
__global__ void k_self(const float* __restrict__ feat, const int* __restrict__ nodes,
                       float* __restrict__ out_center) {
    int b = blockIdx.x * 4 + (threadIdx.x >> 6);
    int t = threadIdx.x & 63;
    int node = nodes[b];
    float4 v = *(const float4*)(feat + (size_t)node * F_DIM + 4 * t);
    __nv_bfloat16 h0, h1, h2, h3, l0, l1, l2, l3;
    bf16split(v.x, h0, l0); bf16split(v.y, h1, l1);
    bf16split(v.z, h2, l2); bf16split(v.w, h3, l3);
    size_t base = (size_t)b * CAT_DIM + 4 * t;
    uint2 ph, pl;
    ph.x = pack2(h0, h1); ph.y = pack2(h2, h3);
    pl.x = pack2(l0, l1); pl.y = pack2(l2, l3);
    *(uint2*)(g_cat_hi + base) = ph;
    *(uint2*)(g_cat_lo + base) = pl;
    if (t < 2) out_center[b * 2 + t] = g_scores[node * 2 + t];
}

// ---------------------------------------------------------------------------
// K3: stable top-K=16 by |s1-c|, mean of selected rows -> g_mean hi/lo
// 64 threads per (b,r); whole-row float4 gathers (measured-best config).
// ---------------------------------------------------------------------------
__global__ void k_relsum(const float* __restrict__ feat, const int* __restrict__ nodes,
                         const int* __restrict__ n1, const int* __restrict__ n2,
                         const int* __restrict__ n3) {
    int b = blockIdx.x, r = blockIdx.y, t = threadIdx.x;  // 64 threads

    __shared__ float s_d[D_DIM];
    __shared__ int   s_i[D_DIM];
    __shared__ int   s_sel[K_SEL];

    const int* nb = (r == 0 ? n1 : (r == 1 ? n2 : n3)) + (size_t)b * D_DIM;

    if (t < D_DIM) {
        int idx = nb[t];
        s_i[t] = idx;
        float c = g_scores[nodes[b] * 2 + 1];
        s_d[t] = fabsf(g_scores[idx * 2 + 1] - c);
    }
    __syncthreads();
    if (t < D_DIM) {
        float d = s_d[t];
        int rank = 0;
#pragma unroll
        for (int j = 0; j < D_DIM; j++) {
            float dj = s_d[j];
            rank += (dj < d) || (dj == d && j < t);   // stable, matches jax top_k
        }
        if (rank < K_SEL) s_sel[rank] = s_i[t];
    }
    __syncthreads();

    int sel[K_SEL];
#pragma unroll
    for (int k = 0; k < K_SEL; k++) sel[k] = s_sel[k];

    float4 acc = make_float4(0.f, 0.f, 0.f, 0.f);
#pragma unroll
    for (int k = 0; k < K_SEL; k++) {
        float4 v = *(const float4*)(feat + (size_t)sel[k] * F_DIM + 4 * t);
        acc.x += v.x; acc.y += v.y; acc.z += v.z; acc.w += v.w;
    }
    const float s = 1.0f / K_SEL;
    acc.x *= s; acc.y *= s; acc.z *= s; acc.w *= s;

    __nv_bfloat16 h0, h1, h2, h3, l0, l1, l2, l3;
    bf16split(acc.x, h0, l0); bf16split(acc.y, h1, l1);
    bf16split(acc.z, h2, l2); bf16split(acc.w, h3, l3);
    size_t base = ((size_t)r * B_DIM + b) * F_DIM + 4 * t;
    uint2 ph, pl;
    ph.x = pack2(h0, h1); ph.y = pack2(h2, h3);
    pl.x = pack2(l0, l1); pl.y = pack2(l2, l3);
    *(uint2*)(g_mean_hi + base) = ph;
    *(uint2*)(g_mean_lo + base) = pl;
}

// ---------------------------------------------------------------------------
// K_prep: bf16-split weights + zero dependency counters
// ---------------------------------------------------------------------------
__global__ void k_prep(const float* __restrict__ w1, const float* __restrict__ w2,
                       const float* __restrict__ w3, const float* __restrict__ weight) {
    int idx = blockIdx.x * blockDim.x + threadIdx.x;
    const int NW = 3 * F_DIM * E_DIM;   // 98304
    const int NG = CAT_DIM * E_DIM;     // 81920
    if (idx < B_DIM / 64) g_cnt[idx] = 0;
    if (idx < NW) {
        int r = idx >> 15;
        const float* w = (r == 0 ? w1 : (r == 1 ? w2 : w3));
        float v = w[idx & 32767];
        __nv_bfloat16 h, l; bf16split(v, h, l);
        g_w_hi[idx] = h; g_w_lo[idx] = l;
    } else if (idx < NW + NG) {
        int j = idx - NW;
        float v = weight[j];
        __nv_bfloat16 h, l; bf16split(v, h, l);
        g_wgt_hi[j] = h; g_wgt_lo[j] = l;
    }
}

// ---------------------------------------------------------------------------
// Shared GEMM chunk engine (R9-measured inner loop, unchanged):
// accumulates chunks [c0, c1) of C[64,BN] += A[64,K] @ B[K,BN] split bf16
// 3-term (Ah*Bh + Ah*Bl + Al*Bh), fp32 accum. 8 warps = 2m x 4n.
// cp.async 2-stage single-sync pipeline.
// ---------------------------------------------------------------------------
#define PA    144            // A row pitch bytes (64 bf16 + 16B pad)
#define SA_SZ (64 * PA)      // 9216

template<int BN>
__device__ __forceinline__ void gemm_chunks(
    uint32_t sb,
    const __nv_bfloat16* __restrict__ At_h, const __nv_bfloat16* __restrict__ At_l,
    const __nv_bfloat16* __restrict__ Bh,  const __nv_bfloat16* __restrict__ Bl,
    int K, int c0, int c1, float (&c)[2][BN / 32][4])
{
    constexpr int JN  = BN / 32;
    constexpr int PBn = BN * 2 + 16;
    constexpr int SBT = 64 * PBn;
    constexpr int STG = 2 * SA_SZ + 2 * SBT;

    int tid  = threadIdx.x;
    int lane = tid & 31;
    int warp = tid >> 5;
    int wm   = warp & 1;
    int wn   = warp >> 1;
    uint32_t aoff = (wm * 32 + (lane & 7) + ((lane >> 3) & 1) * 8) * PA + (lane >> 4) * 16;
    uint32_t boff = ((lane & 7) + ((lane >> 3) & 1) * 8) * PBn + (lane >> 4) * 16
                  + wn * (JN * 8) * 2;

    auto stage_load = [&](uint32_t base, int kofs) {
#pragma unroll
        for (int u = tid; u < 64 * 8; u += 256) {
            int row = u >> 3, c16 = u & 7;
            size_t go = (size_t)row * K + kofs + c16 * 8;
            uint32_t so = row * PA + c16 * 16;
            cp16(base + so,         At_h + go);
            cp16(base + SA_SZ + so, At_l + go);
        }
#pragma unroll
        for (int u = tid; u < 64 * (BN / 8); u += 256) {
            int row = u / (BN / 8), c16 = u % (BN / 8);
            size_t go = (size_t)(kofs + row) * E_DIM + c16 * 8;
            uint32_t so = row * PBn + c16 * 16;
            cp16(base + 2 * SA_SZ + so,       Bh + go);
            cp16(base + 2 * SA_SZ + SBT + so, Bl + go);
        }
    };

    stage_load(sb + (c0 & 1) * STG, c0 * 64);
    CP_COMMIT();

#pragma unroll 1
    for (int ch = c0; ch < c1; ch++) {
        CP_WAIT(0);
        __syncthreads();
        if (ch + 1 < c1) {
            stage_load(sb + ((ch + 1) & 1) * STG, (ch + 1) * 64);
            CP_COMMIT();
        }

        uint32_t base = sb + (ch & 1) * STG;
#pragma unroll
        for (int s = 0; s < 4; s++) {
            uint32_t ah[2][4], al_[2][4];
#pragma unroll
            for (int i = 0; i < 2; i++) {
                ldsm4(ah[i],  base + aoff + i * 16 * PA + 32 * s);
                ldsm4(al_[i], base + SA_SZ + aoff + i * 16 * PA + 32 * s);
            }
            uint32_t bh[JN][2], bl[JN][2];
#pragma unroll
            for (int q = 0; q < JN / 2; q++) {
                uint32_t r4[4];
                ldsm4t(r4, base + 2 * SA_SZ + boff + 16 * s * PBn + q * 32);
                bh[2*q][0] = r4[0]; bh[2*q][1] = r4[1];
                bh[2*q+1][0] = r4[2]; bh[2*q+1][1] = r4[3];
                ldsm4t(r4, base + 2 * SA_SZ + SBT + boff + 16 * s * PBn + q * 32);
                bl[2*q][0] = r4[0]; bl[2*q][1] = r4[1];
                bl[2*q+1][0] = r4[2]; bl[2*q+1][1] = r4[3];
            }
#pragma unroll
            for (int i = 0; i < 2; i++)
#pragma unroll
                for (int j = 0; j < JN; j++) {
                    mma16816(c[i][j], ah[i],  bh[j]);
                    mma16816(c[i][j], ah[i],  bl[j]);
                    mma16816(c[i][j], al_[i], bh[j]);
                }
        }
    }
}

// ---------------------------------------------------------------------------
// K_gemms: single launch, 640 CTAs.
//  bid 0..383   relation tile: mt=bid/3, r=bid%3; C=relu(mean_r@w_r) -> g_cat,
//               then release g_cnt[mt].
//  bid 384..639 final tile: mt=(bid-384)/2, nh=(bid-384)&1;
//               K-chunks 0-3 (self cols, ready at launch) immediately,
//               acquire-spin g_cnt[mt]==3, then chunks 4-9; relu -> out.T
// ---------------------------------------------------------------------------
#define SMEM_G (2 * (2 * SA_SZ + 2 * 64 * (128 * 2 + 16)))   // 106496

__global__ void __launch_bounds__(256, 2)
k_gemms(float* __restrict__ out) {
    extern __shared__ char smem[];
    uint32_t sb = smem_u32(smem);
    int bid  = blockIdx.x;
    int tid  = threadIdx.x;
    int lane = tid & 31;
    int warp = tid >> 5;
    int wm   = warp & 1;
    int wn   = warp >> 1;
    int g    = lane >> 2;
    int tg   = lane & 3;

    if (bid < 384) {
        // ---------------- relation tile ----------------
        int mt = bid / 3, r = bid % 3;
        int m0 = mt * 64;
        const __nv_bfloat16* At_h = g_mean_hi + (size_t)r * B_DIM * F_DIM + (size_t)m0 * F_DIM;
        const __nv_bfloat16* At_l = g_mean_lo + (size_t)r * B_DIM * F_DIM + (size_t)m0 * F_DIM;
        const __nv_bfloat16* Bh   = g_w_hi + (size_t)r * F_DIM * E_DIM;
        const __nv_bfloat16* Bl   = g_w_lo + (size_t)r * F_DIM * E_DIM;
        int colbase = F_DIM + r * E_DIM;

        float c[2][4][4];
#pragma unroll
        for (int i = 0; i < 2; i++)
#pragma unroll
            for (int j = 0; j < 4; j++)
#pragma unroll
                for (int q = 0; q < 4; q++) c[i][j][q] = 0.f;

        gemm_chunks<128>(sb, At_h, At_l, Bh, Bl, F_DIM, 0, 4, c);

#pragma unroll
        for (int i = 0; i < 2; i++) {
#pragma unroll
            for (int j = 0; j < 4; j++) {
                int m = m0 + wm * 32 + i * 16 + g;
                int n = colbase + wn * 32 + j * 8 + tg * 2;
                float x0 = fmaxf(c[i][j][0], 0.f);
                float x1 = fmaxf(c[i][j][1], 0.f);
                float x2 = fmaxf(c[i][j][2], 0.f);
                float x3 = fmaxf(c[i][j][3], 0.f);
                __nv_bfloat16 h0, h1, h2, h3, l0, l1, l2, l3;
                bf16split(x0, h0, l0); bf16split(x1, h1, l1);
                bf16split(x2, h2, l2); bf16split(x3, h3, l3);
                size_t p0 = (size_t)m * CAT_DIM + n;
                size_t p1 = (size_t)(m + 8) * CAT_DIM + n;
                *(uint32_t*)(g_cat_hi + p0) = pack2(h0, h1);
                *(uint32_t*)(g_cat_lo + p0) = pack2(l0, l1);
                *(uint32_t*)(g_cat_hi + p1) = pack2(h2, h3);
                *(uint32_t*)(g_cat_lo + p1) = pack2(l2, l3);
            }
        }
        __threadfence();
        __syncthreads();
        if (tid == 0) red_release(&g_cnt[mt]);
    } else {
        // ---------------- final tile ----------------
        int f  = bid - 384;
        int mt = f >> 1, nh = f & 1;
        int m0 = mt * 64;
        const __nv_bfloat16* At_h = g_cat_hi + (size_t)m0 * CAT_DIM;
        const __nv_bfloat16* At_l = g_cat_lo + (size_t)m0 * CAT_DIM;
        const __nv_bfloat16* Bh   = g_wgt_hi + nh * 64;
        const __nv_bfloat16* Bl   = g_wgt_lo + nh * 64;

        float c[2][2][4];
#pragma unroll
        for (int i = 0; i < 2; i++)
#pragma unroll
            for (int j = 0; j < 2; j++)
#pragma unroll
                for (int q = 0; q < 4; q++) c[i][j][q] = 0.f;

        // chunks 0-3: self columns of g_cat (written by k_self, ready now)
        gemm_chunks<64>(sb, At_h, At_l, Bh, Bl, CAT_DIM, 0, 4, c);

        // wait for this m-block's three relation tiles
        if (tid == 0) {
            while (ld_acquire(&g_cnt[mt]) < 3u) __nanosleep(32);
        }
        __syncthreads();

        // chunks 4-9: relation columns
        gemm_chunks<64>(sb, At_h, At_l, Bh, Bl, CAT_DIM, 4, 10, c);

        // transposed relu store: out[n * 8192 + m]
#pragma unroll
        for (int i = 0; i < 2; i++) {
#pragma unroll
            for (int j = 0; j < 2; j++) {
                int m = m0 + wm * 32 + i * 16 + g;
                int n = nh * 64 + wn * 16 + j * 8 + tg * 2;
                out[(size_t)n * B_DIM + m]           = fmaxf(c[i][j][0], 0.f);
                out[(size_t)(n + 1) * B_DIM + m]     = fmaxf(c[i][j][1], 0.f);
                out[(size_t)n * B_DIM + m + 8]       = fmaxf(c[i][j][2], 0.f);
                out[(size_t)(n + 1) * B_DIM + m + 8] = fmaxf(c[i][j][3], 0.f);
            }
        }
    }
}

// ---------------------------------------------------------------------------
extern "C" void kernel_launch(void* const* d_in, const int* in_sizes, int n_in,
                              void* d_out, int out_size) {
    const float* features = (const float*)d_in[0];
    const int*   nodes    = (const int*)d_in[1];
    const int*   n1       = (const int*)d_in[2];
    const int*   n2       = (const int*)d_in[3];
    const int*   n3       = (const int*)d_in[4];
    const float* wc       = (const float*)d_in[5];
    const float* bc       = (const float*)d_in[6];
    const float* w1       = (const float*)d_in[7];
    const float* w2       = (const float*)d_in[8];
    const float* w3       = (const float*)d_in[9];
    const float* weight   = (const float*)d_in[10];

    float* out_combined = (float*)d_out;                 // 128 x 8192
    float* out_center   = (float*)d_out + E_DIM * B_DIM; // 8192 x 2

    static bool attr_done = false;
    if (!attr_done) {
        cudaFuncSetAttribute(k_gemms, cudaFuncAttributeMaxDynamicSharedMemorySize, SMEM_G);
        attr_done = true;
    }

    // weights prep + counter zeroing
    k_prep<<<(3 * F_DIM * E_DIM + CAT_DIM * E_DIM + 255) / 256, 256>>>(w1, w2, w3, weight);

    // scores for all N
    k_scores<<<(N_NODES + 7) / 8, 256>>>(features, wc, bc);

    // self features -> cat + center scores
    k_self<<<B_DIM / 4, 256>>>(features, nodes, out_center);

    // top-K + mean features (measured-best 64-thread config)
    k_relsum<<<dim3(B_DIM, 3), 64>>>(features, nodes, n1, n2, n3);

    // all four GEMMs in one wave-balanced launch with dependency counters
    k_gemms<<<640, 256, SMEM_G>>>(out_combined);
}

// round 12
// speedup vs baseline: 1.0320x; 1.0320x over previous
#include <cuda_runtime.h>
#include <cuda_bf16.h>
#include <cuda_fp16.h>
#include <cstdint>

#define N_NODES 100000
#define F_DIM   256
#define E_DIM   128
#define B_DIM   8192
#define D_DIM   32
#define K_SEL   16
#define CAT_DIM 640   // F + 3E

// ---------------------------------------------------------------------------
// Scratch (static device globals — no allocations allowed)
// ---------------------------------------------------------------------------
__device__ __align__(16) float          g_scores[N_NODES * 2];
__device__ __align__(16) __half         g_feat_h[(size_t)N_NODES * F_DIM];  // fp16 features
__device__ __align__(16) __nv_bfloat16  g_mean_hi[3ULL * B_DIM * F_DIM];   // [r][m][k]
__device__ __align__(16) __nv_bfloat16  g_mean_lo[3ULL * B_DIM * F_DIM];
__device__ __align__(16) __nv_bfloat16  g_cat_hi[(size_t)B_DIM * CAT_DIM]; // [m][k]
__device__ __align__(16) __nv_bfloat16  g_cat_lo[(size_t)B_DIM * CAT_DIM];
__device__ __align__(16) __nv_bfloat16  g_w_hi[3 * F_DIM * E_DIM];         // [r][k][n]
__device__ __align__(16) __nv_bfloat16  g_w_lo[3 * F_DIM * E_DIM];
__device__ __align__(16) __nv_bfloat16  g_wgt_hi[CAT_DIM * E_DIM];         // [k][n]
__device__ __align__(16) __nv_bfloat16  g_wgt_lo[CAT_DIM * E_DIM];

// ---------------------------------------------------------------------------
// helpers
// ---------------------------------------------------------------------------
__device__ __forceinline__ uint32_t smem_u32(const void* p) {
    uint32_t a;
    asm("{ .reg .u64 t; cvta.to.shared.u64 t, %1; cvt.u32.u64 %0, t; }" : "=r"(a) : "l"(p));
    return a;
}
__device__ __forceinline__ void bf16split(float x, __nv_bfloat16& h, __nv_bfloat16& l) {
    h = __float2bfloat16(x);
    l = __float2bfloat16(x - __bfloat162float(h));
}
__device__ __forceinline__ uint32_t pack2(__nv_bfloat16 a, __nv_bfloat16 b) {
    __nv_bfloat162 t = __halves2bfloat162(a, b);
    return *reinterpret_cast<uint32_t*>(&t);
}
__device__ __forceinline__ void ldsm4(uint32_t* r, uint32_t addr) {
    asm volatile("ldmatrix.sync.aligned.m8n8.x4.shared.b16 {%0,%1,%2,%3}, [%4];"
                 : "=r"(r[0]), "=r"(r[1]), "=r"(r[2]), "=r"(r[3]) : "r"(addr));
}
__device__ __forceinline__ void ldsm4t(uint32_t* r, uint32_t addr) {
    asm volatile("ldmatrix.sync.aligned.m8n8.x4.trans.shared.b16 {%0,%1,%2,%3}, [%4];"
                 : "=r"(r[0]), "=r"(r[1]), "=r"(r[2]), "=r"(r[3]) : "r"(addr));
}
__device__ __forceinline__ void mma16816(float* c, const uint32_t* a, const uint32_t* b) {
    asm volatile(
        "mma.sync.aligned.m16n8k16.row.col.f32.bf16.bf16.f32 "
        "{%0,%1,%2,%3}, {%4,%5,%6,%7}, {%8,%9}, {%0,%1,%2,%3};"
        : "+f"(c[0]), "+f"(c[1]), "+f"(c[2]), "+f"(c[3])
        : "r"(a[0]), "r"(a[1]), "r"(a[2]), "r"(a[3]), "r"(b[0]), "r"(b[1]));
}
__device__ __forceinline__ void cp16(uint32_t s, const void* g) {
    asm volatile("cp.async.cg.shared.global [%0], [%1], 16;" :: "r"(s), "l"(g));
}
#define CP_COMMIT() asm volatile("cp.async.commit_group;" ::: "memory")
#define CP_WAIT(n)  asm volatile("cp.async.wait_group %0;" :: "n"(n) : "memory")

// ---------------------------------------------------------------------------
// K1: scores[n] = features[n] @ wc + bc (one warp per node)
//     + emit fp16 copy of features (row already in registers)
// ---------------------------------------------------------------------------
__global__ void k_scores(const float* __restrict__ feat, const float* __restrict__ wc,
                         const float* __restrict__ bc) {
    int gwarp = (blockIdx.x * blockDim.x + threadIdx.x) >> 5;
    int lane  = threadIdx.x & 31;
    if (gwarp >= N_NODES) return;
    const float* row = feat + (size_t)gwarp * F_DIM;
    __half* hrow = g_feat_h + (size_t)gwarp * F_DIM;
    float s0 = 0.f, s1 = 0.f;
#pragma unroll
    for (int k = 0; k < 8; k++) {
        int f = k * 32 + lane;
        float v = row[f];
        hrow[f] = __float2half(v);
        s0 += v * __ldg(&wc[f * 2 + 0]);
        s1 += v * __ldg(&wc[f * 2 + 1]);
    }
#pragma unroll
    for (int o = 16; o; o >>= 1) {
        s0 += __shfl_down_sync(0xFFFFFFFFu, s0, o);
        s1 += __shfl_down_sync(0xFFFFFFFFu, s1, o);
    }
    if (lane == 0) {
        g_scores[gwarp * 2 + 0] = s0 + bc[0];
        g_scores[gwarp * 2 + 1] = s1 + bc[1];
    }
}

// ---------------------------------------------------------------------------
// K2: self features -> g_cat cols [0,256) + center scores (4 rows / block)
//     (reads fp32 features: exact self-path)
// ---------------------------------------------------------------------------
__global__ void k_self(const float* __restrict__ feat, const int* __restrict__ nodes,
                       float* __restrict__ out_center) {
    int b = blockIdx.x * 4 + (threadIdx.x >> 6);
    int t = threadIdx.x & 63;
    int node = nodes[b];
    float4 v = *(const float4*)(feat + (size_t)node * F_DIM + 4 * t);
    __nv_bfloat16 h0, h1, h2, h3, l0, l1, l2, l3;
    bf16split(v.x, h0, l0); bf16split(v.y, h1, l1);
    bf16split(v.z, h2, l2); bf16split(v.w, h3, l3);
    size_t base = (size_t)b * CAT_DIM + 4 * t;
    uint2 ph, pl;
    ph.x = pack2(h0, h1); ph.y = pack2(h2, h3);
    pl.x = pack2(l0, l1); pl.y = pack2(l2, l3);
    *(uint2*)(g_cat_hi + base) = ph;
    *(uint2*)(g_cat_lo + base) = pl;
    if (t < 2) out_center[b * 2 + t] = g_scores[node * 2 + t];
}

// ---------------------------------------------------------------------------
// K3: stable top-K=16 by |s1-c| (fp32 scores -> identical selection),
// gather-mean from fp16 feature copy (half the bytes), fp32 accumulate,
// split-bf16 store to g_mean. 64 threads per (b,r), 4 cols/thread.
// ---------------------------------------------------------------------------
__global__ void k_relsum(const int* __restrict__ nodes,
                         const int* __restrict__ n1, const int* __restrict__ n2,
                         const int* __restrict__ n3) {
    int b = blockIdx.x, r = blockIdx.y, t = threadIdx.x;  // 64 threads

    __shared__ float s_d[D_DIM];
    __shared__ int   s_i[D_DIM];
    __shared__ int   s_sel[K_SEL];

    const int* nb = (r == 0 ? n1 : (r == 1 ? n2 : n3)) + (size_t)b * D_DIM;

    if (t < D_DIM) {
        int idx = nb[t];
        s_i[t] = idx;
        float c = g_scores[nodes[b] * 2 + 1];
        s_d[t] = fabsf(g_scores[idx * 2 + 1] - c);
    }
    __syncthreads();
    if (t < D_DIM) {
        float d = s_d[t];
        int rank = 0;
#pragma unroll
        for (int j = 0; j < D_DIM; j++) {
            float dj = s_d[j];
            rank += (dj < d) || (dj == d && j < t);   // stable, matches jax top_k
        }
        if (rank < K_SEL) s_sel[rank] = s_i[t];
    }
    __syncthreads();

    int sel[K_SEL];
#pragma unroll
    for (int k = 0; k < K_SEL; k++) sel[k] = s_sel[k];

    float4 acc = make_float4(0.f, 0.f, 0.f, 0.f);
#pragma unroll
    for (int k = 0; k < K_SEL; k++) {
        uint2 u = *(const uint2*)(g_feat_h + (size_t)sel[k] * F_DIM + 4 * t);
        __half2 h01 = *reinterpret_cast<__half2*>(&u.x);
        __half2 h23 = *reinterpret_cast<__half2*>(&u.y);
        float2 f01 = __half22float2(h01);
        float2 f23 = __half22float2(h23);
        acc.x += f01.x; acc.y += f01.y; acc.z += f23.x; acc.w += f23.y;
    }
    const float s = 1.0f / K_SEL;
    acc.x *= s; acc.y *= s; acc.z *= s; acc.w *= s;

    __nv_bfloat16 h0, h1, h2, h3, l0, l1, l2, l3;
    bf16split(acc.x, h0, l0); bf16split(acc.y, h1, l1);
    bf16split(acc.z, h2, l2); bf16split(acc.w, h3, l3);
    size_t base = ((size_t)r * B_DIM + b) * F_DIM + 4 * t;
    uint2 ph, pl;
    ph.x = pack2(h0, h1); ph.y = pack2(h2, h3);
    pl.x = pack2(l0, l1); pl.y = pack2(l2, l3);
    *(uint2*)(g_mean_hi + base) = ph;
    *(uint2*)(g_mean_lo + base) = pl;
}

// ---------------------------------------------------------------------------
// K_prep: bf16-split weights (already [K][N] layout — no transpose)
// ---------------------------------------------------------------------------
__global__ void k_prep(const float* __restrict__ w1, const float* __restrict__ w2,
                       const float* __restrict__ w3, const float* __restrict__ weight) {
    int idx = blockIdx.x * blockDim.x + threadIdx.x;
    const int NW = 3 * F_DIM * E_DIM;   // 98304
    const int NG = CAT_DIM * E_DIM;     // 81920
    if (idx < NW) {
        int r = idx >> 15;
        const float* w = (r == 0 ? w1 : (r == 1 ? w2 : w3));
        float v = w[idx & 32767];
        __nv_bfloat16 h, l; bf16split(v, h, l);
        g_w_hi[idx] = h; g_w_lo[idx] = l;
    } else if (idx < NW + NG) {
        int j = idx - NW;
        float v = weight[j];
        __nv_bfloat16 h, l; bf16split(v, h, l);
        g_wgt_hi[j] = h; g_wgt_lo[j] = l;
    }
}

// ---------------------------------------------------------------------------
// HMMA GEMM, cp.async 2-stage single-sync pipeline (R9-measured).
// C[64,BN] tile = A[64,K] @ B[K,BN]; split bf16 3-term, fp32 accum.
// 8 warps = 2m x 4n; warp tile 32 x (BN/4).
// mode 0 (BN=128): blockIdx.y = relation; relu -> bf16 split -> g_cat cols.
// mode 1 (BN=64):  blockIdx.y = n-half;  relu -> out.T
// ---------------------------------------------------------------------------
#define PA 144        // A row pitch bytes (64 bf16 + 16B pad)
#define BM 64
#define SA_SZ (BM * PA)

template<int BN>
__global__ void __launch_bounds__(256, 2)
k_gemm(const __nv_bfloat16* __restrict__ Ah, const __nv_bfloat16* __restrict__ Al,
       const __nv_bfloat16* __restrict__ Bh, const __nv_bfloat16* __restrict__ Bl,
       int K, int mode, float* __restrict__ out) {
    constexpr int JN   = BN / 32;          // 8-col n fragments per warp
    constexpr int PBn  = BN * 2 + 16;      // B row pitch bytes
    constexpr int SBT  = 64 * PBn;
    constexpr int STG  = 2 * SA_SZ + 2 * SBT;

    extern __shared__ char smem[];
    uint32_t sb = smem_u32(smem);

    int tid  = threadIdx.x;
    int lane = tid & 31;
    int warp = tid >> 5;
    int wm   = warp & 1;      // 2 warps along m
    int wn   = warp >> 1;     // 4 warps along n
    int m0   = blockIdx.x * BM;
    int colbase = 0;          // mode 0: g_cat col base; mode 1: out n base

    if (mode == 0) {
        int r = blockIdx.y;
        Ah += (size_t)r * B_DIM * K;
        Al += (size_t)r * B_DIM * K;
        Bh += (size_t)r * K * E_DIM;
        Bl += (size_t)r * K * E_DIM;
        colbase = F_DIM + r * E_DIM;
    } else {
        int nb = blockIdx.y * BN;
        Bh += nb;  Bl += nb;
        colbase = nb;
    }
    const __nv_bfloat16* At_h = Ah + (size_t)m0 * K;
    const __nv_bfloat16* At_l = Al + (size_t)m0 * K;

    uint32_t aoff = (wm * 32 + (lane & 7) + ((lane >> 3) & 1) * 8) * PA + (lane >> 4) * 16;
    uint32_t boff = ((lane & 7) + ((lane >> 3) & 1) * 8) * PBn + (lane >> 4) * 16
                  + wn * (JN * 8) * 2;

    float c[2][JN][4];
#pragma unroll
    for (int i = 0; i < 2; i++)
#pragma unroll
        for (int j = 0; j < JN; j++)
#pragma unroll
            for (int q = 0; q < 4; q++) c[i][j][q] = 0.f;

    const int NC = K >> 6;

    auto stage_load = [&](uint32_t base, int kofs) {
#pragma unroll
        for (int u = tid; u < BM * 8; u += 256) {
            int row = u >> 3, c16 = u & 7;
            size_t go = (size_t)row * K + kofs + c16 * 8;
            uint32_t so = row * PA + c16 * 16;
            cp16(base + so,         At_h + go);
            cp16(base + SA_SZ + so, At_l + go);
        }
#pragma unroll
        for (int u = tid; u < 64 * (BN / 8); u += 256) {
            int row = u / (BN / 8), c16 = u % (BN / 8);
            size_t go = (size_t)(kofs + row) * E_DIM + c16 * 8;
            uint32_t so = row * PBn + c16 * 16;
            cp16(base + 2 * SA_SZ + so,       Bh + go);
            cp16(base + 2 * SA_SZ + SBT + so, Bl + go);
        }
    };

    stage_load(sb, 0);
    CP_COMMIT();

#pragma unroll 1
    for (int ch = 0; ch < NC; ch++) {
        CP_WAIT(0);
        __syncthreads();
        // safe: all warps finished compute(ch-1); buffer (ch+1)&1 == (ch-1)&1 free
        if (ch + 1 < NC) {
            stage_load(sb + ((ch + 1) & 1) * STG, (ch + 1) * 64);
            CP_COMMIT();
        }

        uint32_t base = sb + (ch & 1) * STG;
#pragma unroll
        for (int s = 0; s < 4; s++) {
            uint32_t ah[2][4], al_[2][4];
#pragma unroll
            for (int i = 0; i < 2; i++) {
                ldsm4(ah[i],  base + aoff + i * 16 * PA + 32 * s);
                ldsm4(al_[i], base + SA_SZ + aoff + i * 16 * PA + 32 * s);
            }
            uint32_t bh[JN][2], bl[JN][2];
#pragma unroll
            for (int q = 0; q < JN / 2; q++) {
                uint32_t r4[4];
                ldsm4t(r4, base + 2 * SA_SZ + boff + 16 * s * PBn + q * 32);
                bh[2*q][0] = r4[0]; bh[2*q][1] = r4[1];
                bh[2*q+1][0] = r4[2]; bh[2*q+1][1] = r4[3];
                ldsm4t(r4, base + 2 * SA_SZ + SBT + boff + 16 * s * PBn + q * 32);
                bl[2*q][0] = r4[0]; bl[2*q][1] = r4[1];
                bl[2*q+1][0] = r4[2]; bl[2*q+1][1] = r4[3];
            }
#pragma unroll
            for (int i = 0; i < 2; i++)
#pragma unroll
                for (int j = 0; j < JN; j++) {
                    mma16816(c[i][j], ah[i],  bh[j]);
                    mma16816(c[i][j], ah[i],  bl[j]);
                    mma16816(c[i][j], al_[i], bh[j]);
                }
        }
    }

    int g  = lane >> 2;
    int tg = lane & 3;
#pragma unroll
    for (int i = 0; i < 2; i++) {
#pragma unroll
        for (int j = 0; j < JN; j++) {
            int m = m0 + wm * 32 + i * 16 + g;
            int n = colbase + wn * (JN * 8) + j * 8 + tg * 2;
            float x0 = fmaxf(c[i][j][0], 0.f);
            float x1 = fmaxf(c[i][j][1], 0.f);
            float x2 = fmaxf(c[i][j][2], 0.f);
            float x3 = fmaxf(c[i][j][3], 0.f);
            if (mode == 0) {
                __nv_bfloat16 h0, h1, h2, h3, l0, l1, l2, l3;
                bf16split(x0, h0, l0); bf16split(x1, h1, l1);
                bf16split(x2, h2, l2); bf16split(x3, h3, l3);
                size_t p0 = (size_t)m * CAT_DIM + n;
                size_t p1 = (size_t)(m + 8) * CAT_DIM + n;
                *(uint32_t*)(g_cat_hi + p0) = pack2(h0, h1);
                *(uint32_t*)(g_cat_lo + p0) = pack2(l0, l1);
                *(uint32_t*)(g_cat_hi + p1) = pack2(h2, h3);
                *(uint32_t*)(g_cat_lo + p1) = pack2(l2, l3);
            } else {
                out[(size_t)n * B_DIM + m]           = x0;
                out[(size_t)(n + 1) * B_DIM + m]     = x1;
                out[(size_t)n * B_DIM + m + 8]       = x2;
                out[(size_t)(n + 1) * B_DIM + m + 8] = x3;
            }
        }
    }
}

#define SMEM_G128 (2 * (2 * SA_SZ + 2 * 64 * (128 * 2 + 16)))   // 106496
#define SMEM_G64  (2 * (2 * SA_SZ + 2 * 64 * (64 * 2 + 16)))    // 73728

// ---------------------------------------------------------------------------
extern "C" void kernel_launch(void* const* d_in, const int* in_sizes, int n_in,
                              void* d_out, int out_size) {
    const float* features = (const float*)d_in[0];
    const int*   nodes    = (const int*)d_in[1];
    const int*   n1       = (const int*)d_in[2];
    const int*   n2       = (const int*)d_in[3];
    const int*   n3       = (const int*)d_in[4];
    const float* wc       = (const float*)d_in[5];
    const float* bc       = (const float*)d_in[6];
    const float* w1       = (const float*)d_in[7];
    const float* w2       = (const float*)d_in[8];
    const float* w3       = (const float*)d_in[9];
    const float* weight   = (const float*)d_in[10];

    float* out_combined = (float*)d_out;                 // 128 x 8192
    float* out_center   = (float*)d_out + E_DIM * B_DIM; // 8192 x 2

    static bool attr_done = false;
    static __nv_bfloat16 *p_mean_hi, *p_mean_lo, *p_cat_hi, *p_cat_lo;
    static __nv_bfloat16 *p_w_hi, *p_w_lo, *p_wgt_hi, *p_wgt_lo;
    if (!attr_done) {
        cudaFuncSetAttribute(k_gemm<128>, cudaFuncAttributeMaxDynamicSharedMemorySize, SMEM_G128);
        cudaFuncSetAttribute(k_gemm<64>,  cudaFuncAttributeMaxDynamicSharedMemorySize, SMEM_G64);
        cudaGetSymbolAddress((void**)&p_mean_hi, g_mean_hi);
        cudaGetSymbolAddress((void**)&p_mean_lo, g_mean_lo);
        cudaGetSymbolAddress((void**)&p_cat_hi,  g_cat_hi);
        cudaGetSymbolAddress((void**)&p_cat_lo,  g_cat_lo);
        cudaGetSymbolAddress((void**)&p_w_hi,    g_w_hi);
        cudaGetSymbolAddress((void**)&p_w_lo,    g_w_lo);
        cudaGetSymbolAddress((void**)&p_wgt_hi,  g_wgt_hi);
        cudaGetSymbolAddress((void**)&p_wgt_lo,  g_wgt_lo);
        attr_done = true;
    }

    // weights prep (independent of scores)
    k_prep<<<(3 * F_DIM * E_DIM + CAT_DIM * E_DIM + 255) / 256, 256>>>(w1, w2, w3, weight);

    // scores + fp16 feature copy
    k_scores<<<(N_NODES + 7) / 8, 256>>>(features, wc, bc);

    // self features -> cat + center scores
    k_self<<<B_DIM / 4, 256>>>(features, nodes, out_center);

    // top-K + mean features (fp16 gather, half the bytes)
    k_relsum<<<dim3(B_DIM, 3), 64>>>(nodes, n1, n2, n3);

    // relation GEMMs: relu(mean @ w_r) -> cat columns (BN=128, grid 128x3)
    k_gemm<128><<<dim3(B_DIM / BM, 3), 256, SMEM_G128>>>(
        p_mean_hi, p_mean_lo, p_w_hi, p_w_lo, F_DIM, 0, out_combined);

    // final GEMM: relu(cat @ weight).T -> out (BN=64, grid 128x2 = 256 CTAs)
    k_gemm<64><<<dim3(B_DIM / BM, 2), 256, SMEM_G64>>>(
        p_cat_hi, p_cat_lo, p_wgt_hi, p_wgt_lo, CAT_DIM, 1, out_combined);
}